// round 16
// baseline (speedup 1.0000x reference)
#include <cuda_runtime.h>
#include <cuda_bf16.h>
#include <cstdint>

#define NN 50000
#define EE 800000
#define BCAP 64           // max in-degree ~38; 64 is >6-sigma safe
#define GT 391            // 128-row GEMM CTAs
#define GB 1563           // bucket-build blocks (512 edges each)

// ---------------- scratch (static device globals; no allocation) ----------------
__device__ int   g_cnt[NN];
__device__ int   g_bucket[(size_t)NN * BCAP];
__device__ float g_dinv[NN];
__device__ float g_h2 [(size_t)NN * 64];
__device__ float g_h2s[(size_t)NN * 64];
__device__ float g_S1 [(size_t)NN * 64];
__device__ float g_S1s[(size_t)NN * 64];
__device__ float g_S2 [(size_t)NN * 64];
__device__ float g_c1 [(size_t)NN * 64];
__device__ float g_c1s[(size_t)NN * 64];
__device__ float g_c2 [(size_t)NN * 64];
__device__ float g_P  [(size_t)NN * 64];
__device__ float g_Wt1[3 * 64 * 64];
__device__ float g_Wt2[3 * 64 * 64];

__device__ __forceinline__ uint32_t pack_bf16(float a, float b) {
    __nv_bfloat162 t = __floats2bfloat162_rn(a, b);
    return *reinterpret_cast<uint32_t*>(&t);
}

__device__ __forceinline__ void split2(float a, float b, uint32_t& hi, uint32_t& lo) {
    __nv_bfloat16 ah = __float2bfloat16(a), bh = __float2bfloat16(b);
    __nv_bfloat162 hv; hv.x = ah; hv.y = bh;
    hi = *reinterpret_cast<uint32_t*>(&hv);
    lo = pack_bf16(a - __bfloat162float(ah), b - __bfloat162float(bh));
}

__device__ __forceinline__ void split4store(uint32_t* Hi, uint32_t* Lo, int w, float4 v) {
    uint32_t h0, l0, h1, l1;
    split2(v.x, v.y, h0, l0);
    split2(v.z, v.w, h1, l1);
    Hi[w] = h0; Hi[w + 1] = h1;
    Lo[w] = l0; Lo[w + 1] = l1;
}

__device__ __forceinline__ void mma16816(float* c, const uint32_t* a, uint32_t b0, uint32_t b1) {
    asm volatile(
        "mma.sync.aligned.m16n8k16.row.col.f32.bf16.bf16.f32 "
        "{%0,%1,%2,%3}, {%4,%5,%6,%7}, {%8,%9}, {%0,%1,%2,%3};"
        : "+f"(c[0]), "+f"(c[1]), "+f"(c[2]), "+f"(c[3])
        : "r"(a[0]), "r"(a[1]), "r"(a[2]), "r"(a[3]), "r"(b0), "r"(b1));
}

__device__ __forceinline__ void ldsm_x4(uint32_t addr, uint32_t* r) {
    asm volatile("ldmatrix.sync.aligned.m8n8.x4.shared.b16 {%0,%1,%2,%3}, [%4];"
                 : "=r"(r[0]), "=r"(r[1]), "=r"(r[2]), "=r"(r[3]) : "r"(addr));
}
__device__ __forceinline__ void ldsm_x2(uint32_t addr, uint32_t* r) {
    asm volatile("ldmatrix.sync.aligned.m8n8.x2.shared.b16 {%0,%1}, [%2];"
                 : "=r"(r[0]), "=r"(r[1]) : "r"(addr));
}

// 3-term bf16 split mainloop; PW/4 must be odd for conflict-free LDSM.
template <int PW, int NK>
__device__ __forceinline__ void run_mainloop(uint32_t smbase, int TA_w, int TB_w,
                                             int baseB_w, int wrow, int nt0,
                                             int lane, float acc[4][4]) {
    const int mA = lane >> 3;
    const uint32_t aH = smbase + (((wrow + (lane & 7) + (mA & 1) * 8) * PW + (mA >> 1) * 4) << 2);
    const uint32_t aL = aH + (TA_w << 2);
    const int l15 = lane & 15;
    uint32_t bH[4], bL[4];
#pragma unroll
    for (int nt = 0; nt < 4; nt++) {
        bH[nt] = smbase + ((baseB_w + ((nt0 + nt) * 8 + (l15 & 7)) * PW + (l15 >> 3) * 4) << 2);
        bL[nt] = bH[nt] + (TB_w << 2);
    }
#pragma unroll
    for (int ks = 0; ks < NK; ks++) {
        const uint32_t kb = (uint32_t)ks * 32;
        uint32_t ah[4], al[4];
        ldsm_x4(aH + kb, ah);
        ldsm_x4(aL + kb, al);
#pragma unroll
        for (int nt = 0; nt < 4; nt++) {
            uint32_t bh[2], bl[2];
            ldsm_x2(bH[nt] + kb, bh);
            ldsm_x2(bL[nt] + kb, bl);
            mma16816(acc[nt], ah, bh[0], bh[1]);
            mma16816(acc[nt], al, bh[0], bh[1]);
            mma16816(acc[nt], ah, bl[0], bl[1]);
        }
    }
}

// ===== dinv + pre-scale: g_dinv[n] = rsqrt(max(cnt,1)); hs = h * dinv (warp/node) =====
__global__ void __launch_bounds__(256) dinv_scale_kernel(const float* __restrict__ h,
                                                         float* __restrict__ hs) {
    int n = (blockIdx.x * 256 + threadIdx.x) >> 5;
    if (n >= NN) return;
    int lane = threadIdx.x & 31;
    int c = g_cnt[n];
    float d = rsqrtf((float)(c > 0 ? c : 1));
    if (lane == 0) g_dinv[n] = d;
    float2 v = *(const float2*)(h + (size_t)n * 64 + lane * 2);
    *(float2*)(hs + (size_t)n * 64 + lane * 2) = make_float2(v.x * d, v.y * d);
}

// ===== 64-K GEMM term: T = X[128rows,64] @ W64[64,64]^T =====
// MODE 0: P = T    MODE 1: P += T    MODE 2: out = relu(P + T + bias)  (+outs = out*dinv)
template <int MODE>
__global__ void __launch_bounds__(512) gemm64_term_kernel(const float* __restrict__ X,
                                                          const float* __restrict__ W64,
                                                          float* __restrict__ P,
                                                          const float* __restrict__ bias,
                                                          float* __restrict__ outp,
                                                          float* __restrict__ outs) {
    constexpr int PW = 36, TA = 128 * PW, TB = 64 * PW;
    extern __shared__ uint32_t sm[];
    const int tid = threadIdx.x;
    const long row0 = (long)blockIdx.x * 128;

    for (int q = tid; q < 128 * 16; q += 512) {
        int r = q >> 4, c = (q & 15) * 4;
        long gr = row0 + r; if (gr >= NN) gr = NN - 1;
        float4 v = *(const float4*)(X + gr * 64 + c);
        split4store(sm, sm + TA, r * PW + (c >> 1), v);
    }
    for (int q = tid; q < 64 * 16; q += 512) {
        int r = q >> 4, c = (q & 15) * 4;
        float4 v = *(const float4*)(W64 + (long)r * 64 + c);
        split4store(sm + 2 * TA, sm + 2 * TA + TB, r * PW + (c >> 1), v);
    }
    __syncthreads();

    const int warp = tid >> 5, lane = tid & 31;
    const int wrow = (warp & 7) * 16;
    const int nt0 = (warp >> 3) * 4;
    const uint32_t smbase = (uint32_t)__cvta_generic_to_shared(sm);

    float acc[4][4];
#pragma unroll
    for (int nt = 0; nt < 4; nt++)
#pragma unroll
        for (int j = 0; j < 4; j++) acc[nt][j] = 0.f;
    run_mainloop<PW, 4>(smbase, TA, TB, 2 * TA, wrow, nt0, lane, acc);

    const int rA = lane >> 2, kq = lane & 3;
    const long r_lo = row0 + wrow + rA, r_hi = r_lo + 8;
    float d_lo = 0.f, d_hi = 0.f;
    if (MODE == 2 && outs) {
        if (r_lo < NN) d_lo = g_dinv[r_lo];
        if (r_hi < NN) d_hi = g_dinv[r_hi];
    }
#pragma unroll
    for (int nt = 0; nt < 4; nt++) {
        int col = (nt0 + nt) * 8 + kq * 2;
        if (MODE == 0) {
            if (r_lo < NN) *(float2*)(P + r_lo * 64 + col) = make_float2(acc[nt][0], acc[nt][1]);
            if (r_hi < NN) *(float2*)(P + r_hi * 64 + col) = make_float2(acc[nt][2], acc[nt][3]);
        } else if (MODE == 1) {
            if (r_lo < NN) {
                float2 p = *(float2*)(P + r_lo * 64 + col);
                *(float2*)(P + r_lo * 64 + col) = make_float2(p.x + acc[nt][0], p.y + acc[nt][1]);
            }
            if (r_hi < NN) {
                float2 p = *(float2*)(P + r_hi * 64 + col);
                *(float2*)(P + r_hi * 64 + col) = make_float2(p.x + acc[nt][2], p.y + acc[nt][3]);
            }
        } else {
            float b0 = __ldg(bias + col), b1 = __ldg(bias + col + 1);
            if (r_lo < NN) {
                float2 p = *(float2*)(P + r_lo * 64 + col);
                float2 v = make_float2(fmaxf(p.x + acc[nt][0] + b0, 0.f),
                                       fmaxf(p.y + acc[nt][1] + b1, 0.f));
                *(float2*)(outp + r_lo * 64 + col) = v;
                if (outs) *(float2*)(outs + r_lo * 64 + col) = make_float2(v.x * d_lo, v.y * d_lo);
            }
            if (r_hi < NN) {
                float2 p = *(float2*)(P + r_hi * 64 + col);
                float2 v = make_float2(fmaxf(p.x + acc[nt][2] + b0, 0.f),
                                       fmaxf(p.y + acc[nt][3] + b1, 0.f));
                *(float2*)(outp + r_hi * 64 + col) = v;
                if (outs) *(float2*)(outs + r_hi * 64 + col) = make_float2(v.x * d_hi, v.y * d_hi);
            }
        }
    }
}

// =========== fused front MLP + bucket build + weight transforms ===========
__global__ void __launch_bounds__(512) front_build_kernel(const float* __restrict__ X,
                                                          const float* __restrict__ W1,
                                                          const float* __restrict__ b1,
                                                          const float* __restrict__ W2,
                                                          const float* __restrict__ b2,
                                                          float* __restrict__ out,
                                                          const int* __restrict__ src,
                                                          const int* __restrict__ dst,
                                                          const float* __restrict__ Wc1,
                                                          const float* __restrict__ Wc2,
                                                          float* __restrict__ Wt1,
                                                          float* __restrict__ Wt2) {
    extern __shared__ uint32_t sm[];
    const int b = blockIdx.x;
    const int tid = threadIdx.x;

    if (b >= GT) {
        if (b < GT + GB) {                       // bucket build
            int e = (b - GT) * 512 + tid;
            if (e < EE) {
                int d = dst[e];
                int p = atomicAdd(&g_cnt[d], 1);
                if (p < BCAP) g_bucket[(size_t)d * BCAP + p] = src[e];
            }
        } else {                                 // weight transforms: [W0-W2 | -W1 | 2W2]
            const float* W = (b == GT + GB) ? Wc1 : Wc2;
            float* Wt = (b == GT + GB) ? Wt1 : Wt2;
            for (int i = tid; i < 4096; i += 512) {
                int r = i >> 6, c = i & 63;
                float w0 = W[r * 192 + c], w1 = W[r * 192 + 64 + c], w2 = W[r * 192 + 128 + c];
                Wt[i]        = w0 - w2;
                Wt[4096 + i] = -w1;
                Wt[8192 + i] = 2.f * w2;
            }
        }
        return;
    }

    constexpr int PW1 = 68, TA1 = 128 * PW1, TB1 = 64 * PW1;
    constexpr int PW2 = 36, TA2 = 128 * PW2, TB2 = 64 * PW2;
    __shared__ float bsh1[64], bsh2[64];
    const long row0 = (long)b * 128;
    if (tid < 64) { bsh1[tid] = b1[tid]; bsh2[tid] = b2[tid]; }

    for (int q = tid; q < 128 * 32; q += 512) {
        int r = q >> 5, c = (q & 31) * 4;
        long gr = row0 + r; if (gr >= NN) gr = NN - 1;
        float4 v = *(const float4*)(X + gr * 128 + c);
        split4store(sm, sm + TA1, r * PW1 + (c >> 1), v);
    }
    for (int q = tid; q < 64 * 32; q += 512) {
        int r = q >> 5, c = (q & 31) * 4;
        float4 v = *(const float4*)(W1 + (long)r * 128 + c);
        split4store(sm + 2 * TA1, sm + 2 * TA1 + TB1, r * PW1 + (c >> 1), v);
    }
    __syncthreads();

    const int warp = tid >> 5, lane = tid & 31;
    const int wrow = (warp & 7) * 16;
    const int nt0 = (warp >> 3) * 4;
    const uint32_t smbase = (uint32_t)__cvta_generic_to_shared(sm);

    float acc[4][4];
#pragma unroll
    for (int nt = 0; nt < 4; nt++)
#pragma unroll
        for (int j = 0; j < 4; j++) acc[nt][j] = 0.f;
    run_mainloop<PW1, 8>(smbase, TA1, TB1, 2 * TA1, wrow, nt0, lane, acc);
    __syncthreads();

    {   // h1 = relu(acc+b1) -> restage as KD=64 tiles (overlay)
        const int rA = lane >> 2, kq = lane & 3;
        const int rlo = wrow + rA, rhi = rlo + 8;
#pragma unroll
        for (int nt = 0; nt < 4; nt++) {
            int col = (nt0 + nt) * 8 + kq * 2;
            float v0x = fmaxf(acc[nt][0] + bsh1[col], 0.f);
            float v0y = fmaxf(acc[nt][1] + bsh1[col + 1], 0.f);
            float v1x = fmaxf(acc[nt][2] + bsh1[col], 0.f);
            float v1y = fmaxf(acc[nt][3] + bsh1[col + 1], 0.f);
            int w = col >> 1;
            uint32_t h0, l0, h1, l1;
            split2(v0x, v0y, h0, l0);
            split2(v1x, v1y, h1, l1);
            sm[rlo * PW2 + w]       = h0;
            sm[TA2 + rlo * PW2 + w] = l0;
            sm[rhi * PW2 + w]       = h1;
            sm[TA2 + rhi * PW2 + w] = l1;
        }
    }
    for (int q = tid; q < 64 * 16; q += 512) {
        int r = q >> 4, c = (q & 15) * 4;
        float4 v = *(const float4*)(W2 + (long)r * 64 + c);
        split4store(sm + 2 * TA2, sm + 2 * TA2 + TB2, r * PW2 + (c >> 1), v);
    }
    __syncthreads();

    float acc2[4][4];
#pragma unroll
    for (int nt = 0; nt < 4; nt++)
#pragma unroll
        for (int j = 0; j < 4; j++) acc2[nt][j] = 0.f;
    run_mainloop<PW2, 4>(smbase, TA2, TB2, 2 * TA2, wrow, nt0, lane, acc2);

    const int rA = lane >> 2, kq = lane & 3;
    const long r_lo = row0 + wrow + rA, r_hi = r_lo + 8;
#pragma unroll
    for (int nt = 0; nt < 4; nt++) {
        int col = (nt0 + nt) * 8 + kq * 2;
        float2 v0 = make_float2(fmaxf(acc2[nt][0] + bsh2[col], 0.f),
                                fmaxf(acc2[nt][1] + bsh2[col + 1], 0.f));
        float2 v1 = make_float2(fmaxf(acc2[nt][2] + bsh2[col], 0.f),
                                fmaxf(acc2[nt][3] + bsh2[col + 1], 0.f));
        if (r_lo < NN) *(float2*)(out + r_lo * 64 + col) = v0;
        if (r_hi < NN) *(float2*)(out + r_hi * 64 + col) = v1;
    }
}

// =========== fused back MLP + head ===========
__global__ void __launch_bounds__(512) mlp_back_kernel(const float* __restrict__ X,
                                                       const float* __restrict__ W3,
                                                       const float* __restrict__ b3,
                                                       const float* __restrict__ W4,
                                                       const float* __restrict__ b4,
                                                       float* __restrict__ out) {
    constexpr int PW = 36, TA = 128 * PW, TB = 64 * PW;
    extern __shared__ uint32_t sm[];
    __shared__ float bsh[64], W4sh[128], b4sh[2];
    __shared__ float hp[2][128][2];

    const int tid = threadIdx.x;
    const long row0 = (long)blockIdx.x * 128;
    if (tid < 64)  bsh[tid] = b3[tid];
    if (tid < 128) W4sh[tid] = W4[tid];
    if (tid < 2)   b4sh[tid] = b4[tid];

    for (int q = tid; q < 128 * 16; q += 512) {
        int r = q >> 4, c = (q & 15) * 4;
        long gr = row0 + r; if (gr >= NN) gr = NN - 1;
        float4 v = *(const float4*)(X + gr * 64 + c);
        split4store(sm, sm + TA, r * PW + (c >> 1), v);
    }
    for (int q = tid; q < 64 * 16; q += 512) {
        int r = q >> 4, c = (q & 15) * 4;
        float4 v = *(const float4*)(W3 + (long)r * 64 + c);
        split4store(sm + 2 * TA, sm + 2 * TA + TB, r * PW + (c >> 1), v);
    }
    __syncthreads();

    const int warp = tid >> 5, lane = tid & 31;
    const int wrow = (warp & 7) * 16;
    const int nt0w = warp >> 3;
    const int nt0 = nt0w * 4;
    const uint32_t smbase = (uint32_t)__cvta_generic_to_shared(sm);

    float acc[4][4];
#pragma unroll
    for (int nt = 0; nt < 4; nt++)
#pragma unroll
        for (int j = 0; j < 4; j++) acc[nt][j] = 0.f;
    run_mainloop<PW, 4>(smbase, TA, TB, 2 * TA, wrow, nt0, lane, acc);

    const int rA = lane >> 2, kq = lane & 3;
    float p00 = 0.f, p01 = 0.f, p10 = 0.f, p11 = 0.f;
#pragma unroll
    for (int nt = 0; nt < 4; nt++) {
        int c = (nt0 + nt) * 8 + kq * 2;
        float v0x = fmaxf(acc[nt][0] + bsh[c], 0.f);
        float v0y = fmaxf(acc[nt][1] + bsh[c + 1], 0.f);
        float v1x = fmaxf(acc[nt][2] + bsh[c], 0.f);
        float v1y = fmaxf(acc[nt][3] + bsh[c + 1], 0.f);
        float w0a = W4sh[c], w0b = W4sh[c + 1];
        float w1a = W4sh[64 + c], w1b = W4sh[64 + c + 1];
        p00 = fmaf(v0x, w0a, fmaf(v0y, w0b, p00));
        p01 = fmaf(v0x, w1a, fmaf(v0y, w1b, p01));
        p10 = fmaf(v1x, w0a, fmaf(v1y, w0b, p10));
        p11 = fmaf(v1x, w1a, fmaf(v1y, w1b, p11));
    }
    p00 += __shfl_xor_sync(0xffffffffu, p00, 1); p00 += __shfl_xor_sync(0xffffffffu, p00, 2);
    p01 += __shfl_xor_sync(0xffffffffu, p01, 1); p01 += __shfl_xor_sync(0xffffffffu, p01, 2);
    p10 += __shfl_xor_sync(0xffffffffu, p10, 1); p10 += __shfl_xor_sync(0xffffffffu, p10, 2);
    p11 += __shfl_xor_sync(0xffffffffu, p11, 1); p11 += __shfl_xor_sync(0xffffffffu, p11, 2);
    if (kq == 0) {
        hp[nt0w][wrow + rA][0] = p00;
        hp[nt0w][wrow + rA][1] = p01;
        hp[nt0w][wrow + rA + 8][0] = p10;
        hp[nt0w][wrow + rA + 8][1] = p11;
    }
    __syncthreads();
    if (tid < 256) {
        int row = tid >> 1, cls = tid & 1;
        long gr = row0 + row;
        if (gr < NN) out[gr * 2 + cls] = hp[0][row][cls] + hp[1][row][cls] + b4sh[cls];
    }
}

// ------------- SpMM on pre-scaled input: S[n,:] = dinv[n] * sum_{e: dst=n} Xs[src,:] -------------
__global__ void __launch_bounds__(256) spmm_norm_kernel(const float* __restrict__ Xs,
                                                        float* __restrict__ Sout,
                                                        float* __restrict__ Souts) {
    int n = (blockIdx.x * 256 + threadIdx.x) >> 5;
    if (n >= NN) return;
    int lane = threadIdx.x & 31;
    int cnt = g_cnt[n];
    if (cnt > BCAP) cnt = BCAP;
    const int4* bk4 = (const int4*)&g_bucket[(size_t)n * BCAP];
    const float* xb = Xs + (size_t)lane * 2;
    float2 a0 = make_float2(0.f, 0.f), a1 = make_float2(0.f, 0.f);
    float2 a2 = make_float2(0.f, 0.f), a3 = make_float2(0.f, 0.f);
    int i = 0;
    for (; i + 3 < cnt; i += 4) {
        int4 s4 = bk4[i >> 2];
        float2 v0 = *(const float2*)(xb + (size_t)s4.x * 64);
        float2 v1 = *(const float2*)(xb + (size_t)s4.y * 64);
        float2 v2 = *(const float2*)(xb + (size_t)s4.z * 64);
        float2 v3 = *(const float2*)(xb + (size_t)s4.w * 64);
        a0.x += v0.x; a0.y += v0.y;
        a1.x += v1.x; a1.y += v1.y;
        a2.x += v2.x; a2.y += v2.y;
        a3.x += v3.x; a3.y += v3.y;
    }
    const int* bk = (const int*)bk4;
    for (; i < cnt; i++) {
        int s = bk[i];
        float2 v = *(const float2*)(xb + (size_t)s * 64);
        a0.x += v.x; a0.y += v.y;
    }
    float dn = g_dinv[n];
    float2 acc;
    acc.x = ((a0.x + a1.x) + (a2.x + a3.x)) * dn;
    acc.y = ((a0.y + a1.y) + (a2.y + a3.y)) * dn;
    *(float2*)(Sout + (size_t)n * 64 + lane * 2) = acc;
    if (Souts)
        *(float2*)(Souts + (size_t)n * 64 + lane * 2) = make_float2(acc.x * dn, acc.y * dn);
}

// ---------------- launch ----------------
extern "C" void kernel_launch(void* const* d_in, const int* in_sizes, int n_in,
                              void* d_out, int out_size) {
    const float* in_feat = (const float*)d_in[0];
    const int*   src     = (const int*)d_in[1];
    const int*   dst     = (const int*)d_in[2];
    const float* W1  = (const float*)d_in[3];
    const float* b1  = (const float*)d_in[4];
    const float* W2  = (const float*)d_in[5];
    const float* b2  = (const float*)d_in[6];
    const float* Wc1 = (const float*)d_in[7];
    const float* bc1 = (const float*)d_in[8];
    const float* Wc2 = (const float*)d_in[9];
    const float* bc2 = (const float*)d_in[10];
    const float* W3  = (const float*)d_in[11];
    const float* b3  = (const float*)d_in[12];
    const float* W4  = (const float*)d_in[13];
    const float* b4  = (const float*)d_in[14];
    float* out = (float*)d_out;

    float *h2, *h2s, *S1, *S1s, *S2, *c1, *c1s, *c2, *P, *Wt1, *Wt2;
    int* cnt;
    cudaGetSymbolAddress((void**)&h2,  g_h2);
    cudaGetSymbolAddress((void**)&h2s, g_h2s);
    cudaGetSymbolAddress((void**)&S1,  g_S1);
    cudaGetSymbolAddress((void**)&S1s, g_S1s);
    cudaGetSymbolAddress((void**)&S2,  g_S2);
    cudaGetSymbolAddress((void**)&c1,  g_c1);
    cudaGetSymbolAddress((void**)&c1s, g_c1s);
    cudaGetSymbolAddress((void**)&c2,  g_c2);
    cudaGetSymbolAddress((void**)&P,   g_P);
    cudaGetSymbolAddress((void**)&Wt1, g_Wt1);
    cudaGetSymbolAddress((void**)&Wt2, g_Wt2);
    cudaGetSymbolAddress((void**)&cnt, g_cnt);

    const int FRONT_SMEM = (2 * 128 * 68 + 2 * 64 * 68) * 4;   // 104448
    const int TERM_SMEM  = (2 * 128 * 36 + 2 * 64 * 36) * 4;   // 55296

    cudaFuncSetAttribute(front_build_kernel,   cudaFuncAttributeMaxDynamicSharedMemorySize, FRONT_SMEM);
    cudaFuncSetAttribute(gemm64_term_kernel<0>, cudaFuncAttributeMaxDynamicSharedMemorySize, TERM_SMEM);
    cudaFuncSetAttribute(gemm64_term_kernel<1>, cudaFuncAttributeMaxDynamicSharedMemorySize, TERM_SMEM);
    cudaFuncSetAttribute(gemm64_term_kernel<2>, cudaFuncAttributeMaxDynamicSharedMemorySize, TERM_SMEM);
    cudaFuncSetAttribute(mlp_back_kernel,      cudaFuncAttributeMaxDynamicSharedMemorySize, TERM_SMEM);

    const int GW = (NN * 32 + 255) / 256;   // warp-per-node kernels

    // side stream + events (created per call; intentionally not destroyed —
    // destroying a stream participating in capture is illegal; leak is 2 calls total)
    cudaStream_t s2;
    cudaStreamCreateWithFlags(&s2, cudaStreamNonBlocking);
    cudaEvent_t ev[6];
    for (int i = 0; i < 6; i++) cudaEventCreateWithFlags(&ev[i], cudaEventDisableTiming);

    // zero counts, then fused front-MLP || bucket-build || weight transforms
    cudaMemsetAsync(cnt, 0, NN * sizeof(int));
    front_build_kernel<<<GT + GB + 2, 512, FRONT_SMEM>>>(in_feat, W1, b1, W2, b2, h2,
                                                         src, dst, Wc1, Wc2, Wt1, Wt2);
    dinv_scale_kernel<<<GW, 256>>>(h2, h2s);

    // ===== ChebConv 1 =====
    cudaEventRecord(ev[0], 0);
    cudaStreamWaitEvent(s2, ev[0], 0);
    gemm64_term_kernel<0><<<GT, 512, TERM_SMEM, s2>>>(h2, Wt1, P, nullptr, nullptr, nullptr);
    spmm_norm_kernel<<<GW, 256>>>(h2s, S1, S1s);
    cudaEventRecord(ev[1], 0);
    cudaStreamWaitEvent(s2, ev[1], 0);
    gemm64_term_kernel<1><<<GT, 512, TERM_SMEM, s2>>>(S1, Wt1 + 4096, P, nullptr, nullptr, nullptr);
    cudaEventRecord(ev[2], s2);
    spmm_norm_kernel<<<GW, 256>>>(S1s, S2, nullptr);
    cudaStreamWaitEvent(0, ev[2], 0);
    gemm64_term_kernel<2><<<GT, 512, TERM_SMEM>>>(S2, Wt1 + 8192, P, bc1, c1, c1s);

    // ===== ChebConv 2 =====
    cudaEventRecord(ev[3], 0);
    cudaStreamWaitEvent(s2, ev[3], 0);
    gemm64_term_kernel<0><<<GT, 512, TERM_SMEM, s2>>>(c1, Wt2, P, nullptr, nullptr, nullptr);
    spmm_norm_kernel<<<GW, 256>>>(c1s, S1, S1s);
    cudaEventRecord(ev[4], 0);
    cudaStreamWaitEvent(s2, ev[4], 0);
    gemm64_term_kernel<1><<<GT, 512, TERM_SMEM, s2>>>(S1, Wt2 + 4096, P, nullptr, nullptr, nullptr);
    cudaEventRecord(ev[5], s2);
    spmm_norm_kernel<<<GW, 256>>>(S1s, S2, nullptr);
    cudaStreamWaitEvent(0, ev[5], 0);
    gemm64_term_kernel<2><<<GT, 512, TERM_SMEM>>>(S2, Wt2 + 8192, P, bc2, c2, nullptr);

    // fused back MLP + head
    mlp_back_kernel<<<GT, 512, TERM_SMEM>>>(c2, W3, b3, W4, b4, out);
}

// round 17
// speedup vs baseline: 1.0227x; 1.0227x over previous
#include <cuda_runtime.h>
#include <cuda_bf16.h>
#include <cstdint>

#define NN 50000
#define EE 800000
#define BCAP 64           // max in-degree ~38; 64 is >6-sigma safe
#define GT 391            // 128-row GEMM CTAs
#define GB 1563           // bucket-build blocks (512 edges each)

// ---------------- scratch (static device globals; no allocation) ----------------
__device__ int   g_cnt[NN];
__device__ int   g_bucket[(size_t)NN * BCAP];
__device__ float g_dinv[NN];
__device__ float g_drt [NN];          // sqrt(deg) = 1/dinv
__device__ float g_h2 [(size_t)NN * 64];
__device__ float g_h2s[(size_t)NN * 64];
__device__ float g_S1s[(size_t)NN * 64];
__device__ float g_S2 [(size_t)NN * 64];
__device__ float g_c1s[(size_t)NN * 64];
__device__ float g_c2 [(size_t)NN * 64];

__device__ __forceinline__ uint32_t pack_bf16(float a, float b) {
    __nv_bfloat162 t = __floats2bfloat162_rn(a, b);
    return *reinterpret_cast<uint32_t*>(&t);
}

__device__ __forceinline__ void split2(float a, float b, uint32_t& hi, uint32_t& lo) {
    __nv_bfloat16 ah = __float2bfloat16(a), bh = __float2bfloat16(b);
    __nv_bfloat162 hv; hv.x = ah; hv.y = bh;
    hi = *reinterpret_cast<uint32_t*>(&hv);
    lo = pack_bf16(a - __bfloat162float(ah), b - __bfloat162float(bh));
}

__device__ __forceinline__ void split4store(uint32_t* Hi, uint32_t* Lo, int w, float4 v) {
    uint32_t h0, l0, h1, l1;
    split2(v.x, v.y, h0, l0);
    split2(v.z, v.w, h1, l1);
    Hi[w] = h0; Hi[w + 1] = h1;
    Lo[w] = l0; Lo[w + 1] = l1;
}

__device__ __forceinline__ void mma16816(float* c, const uint32_t* a, uint32_t b0, uint32_t b1) {
    asm volatile(
        "mma.sync.aligned.m16n8k16.row.col.f32.bf16.bf16.f32 "
        "{%0,%1,%2,%3}, {%4,%5,%6,%7}, {%8,%9}, {%0,%1,%2,%3};"
        : "+f"(c[0]), "+f"(c[1]), "+f"(c[2]), "+f"(c[3])
        : "r"(a[0]), "r"(a[1]), "r"(a[2]), "r"(a[3]), "r"(b0), "r"(b1));
}

__device__ __forceinline__ void ldsm_x4(uint32_t addr, uint32_t* r) {
    asm volatile("ldmatrix.sync.aligned.m8n8.x4.shared.b16 {%0,%1,%2,%3}, [%4];"
                 : "=r"(r[0]), "=r"(r[1]), "=r"(r[2]), "=r"(r[3]) : "r"(addr));
}
__device__ __forceinline__ void ldsm_x2(uint32_t addr, uint32_t* r) {
    asm volatile("ldmatrix.sync.aligned.m8n8.x2.shared.b16 {%0,%1}, [%2];"
                 : "=r"(r[0]), "=r"(r[1]) : "r"(addr));
}

// 3-term bf16 split mainloop; PW/4 must be odd for conflict-free LDSM.
template <int PW, int NK>
__device__ __forceinline__ void run_mainloop(uint32_t smbase, int TA_w, int TB_w,
                                             int baseB_w, int wrow, int nt0,
                                             int lane, float acc[4][4]) {
    const int mA = lane >> 3;
    const uint32_t aH = smbase + (((wrow + (lane & 7) + (mA & 1) * 8) * PW + (mA >> 1) * 4) << 2);
    const uint32_t aL = aH + (TA_w << 2);
    const int l15 = lane & 15;
    uint32_t bH[4], bL[4];
#pragma unroll
    for (int nt = 0; nt < 4; nt++) {
        bH[nt] = smbase + ((baseB_w + ((nt0 + nt) * 8 + (l15 & 7)) * PW + (l15 >> 3) * 4) << 2);
        bL[nt] = bH[nt] + (TB_w << 2);
    }
#pragma unroll
    for (int ks = 0; ks < NK; ks++) {
        const uint32_t kb = (uint32_t)ks * 32;
        uint32_t ah[4], al[4];
        ldsm_x4(aH + kb, ah);
        ldsm_x4(aL + kb, al);
#pragma unroll
        for (int nt = 0; nt < 4; nt++) {
            uint32_t bh[2], bl[2];
            ldsm_x2(bH[nt] + kb, bh);
            ldsm_x2(bL[nt] + kb, bl);
            mma16816(acc[nt], ah, bh[0], bh[1]);
            mma16816(acc[nt], al, bh[0], bh[1]);
            mma16816(acc[nt], ah, bl[0], bl[1]);
        }
    }
}

// ===== dinv/drt + pre-scale: hs = h * dinv (warp/node) =====
__global__ void __launch_bounds__(256) dinv_scale_kernel(const float* __restrict__ h,
                                                         float* __restrict__ hs) {
    int n = (blockIdx.x * 256 + threadIdx.x) >> 5;
    if (n >= NN) return;
    int lane = threadIdx.x & 31;
    int c = g_cnt[n];
    float f = (float)(c > 0 ? c : 1);
    float d = rsqrtf(f);
    if (lane == 0) { g_dinv[n] = d; g_drt[n] = sqrtf(f); }
    float2 v = *(const float2*)(h + (size_t)n * 64 + lane * 2);
    *(float2*)(hs + (size_t)n * 64 + lane * 2) = make_float2(v.x * d, v.y * d);
}

// =========== K-chunked cat-GEMM: out = relu([h|-S1|2S2-h] @ W[64,192]^T + b) =========
// S1 is passed pre-scaled (S1s); staging reconstructs S1 = S1s*drt.
// CAT==1: X is unscaled h.  CAT==2: X is scaled (c1s); h = X*drt.
// out (optional): unscaled result.  outs (optional): result*dinv for next spmm hop.
template <int KD, int KC, int CAT>
__global__ void __launch_bounds__(512) gemm_mma_kernel(const float* __restrict__ X,
                                                       const float* __restrict__ S1s,
                                                       const float* __restrict__ S2,
                                                       const float* __restrict__ W,
                                                       const float* __restrict__ bias,
                                                       float* __restrict__ out,
                                                       float* __restrict__ outs,
                                                       int do_relu) {
    constexpr int PW = KC / 2 + 4;
    constexpr int TA = 128 * PW, TB = 64 * PW;
    constexpr int NCH = KD / KC, NK = KC / 16, KQ = KC / 4;
    extern __shared__ uint32_t sm[];
    __shared__ float bsh[64];

    const int tid = threadIdx.x;
    const long row0 = (long)blockIdx.x * 128;
    if (tid < 64) bsh[tid] = bias[tid];

    const int warp = tid >> 5, lane = tid & 31;
    const int wrow = (warp & 7) * 16;
    const int nt0 = (warp >> 3) * 4;
    const uint32_t smbase = (uint32_t)__cvta_generic_to_shared(sm);

    float acc[4][4];
#pragma unroll
    for (int nt = 0; nt < 4; nt++)
#pragma unroll
        for (int j = 0; j < 4; j++) acc[nt][j] = 0.f;

#pragma unroll
    for (int ch = 0; ch < NCH; ch++) {
        if (ch) __syncthreads();
        for (int q = tid; q < 128 * KQ; q += 512) {
            int r = q / KQ, cl = (q % KQ) * 4, gc = ch * KC + cl;
            long gr = row0 + r; if (gr >= NN) gr = NN - 1;
            float4 v;
            if (CAT) {
                float drt = g_drt[gr];
                float hx = (CAT == 2) ? drt : 1.f;       // X -> h multiplier
                if (gc < 64) {
                    float4 x = *(const float4*)(X + gr * 64 + gc);
                    v = make_float4(x.x * hx, x.y * hx, x.z * hx, x.w * hx);
                } else if (gc < 128) {
                    float4 s = *(const float4*)(S1s + gr * 64 + (gc - 64));
                    v = make_float4(-s.x * drt, -s.y * drt, -s.z * drt, -s.w * drt);
                } else {
                    float4 s = *(const float4*)(S2 + gr * 64 + (gc - 128));
                    float4 h = *(const float4*)(X + gr * 64 + (gc - 128));
                    v = make_float4(fmaf(2.f, s.x, -h.x * hx), fmaf(2.f, s.y, -h.y * hx),
                                    fmaf(2.f, s.z, -h.z * hx), fmaf(2.f, s.w, -h.w * hx));
                }
            } else {
                v = *(const float4*)(X + gr * KD + gc);
            }
            split4store(sm, sm + TA, r * PW + (cl >> 1), v);
        }
        for (int q = tid; q < 64 * KQ; q += 512) {
            int r = q / KQ, cl = (q % KQ) * 4, gc = ch * KC + cl;
            float4 v = *(const float4*)(W + (long)r * KD + gc);
            split4store(sm + 2 * TA, sm + 2 * TA + TB, r * PW + (cl >> 1), v);
        }
        __syncthreads();
        run_mainloop<PW, NK>(smbase, TA, TB, 2 * TA, wrow, nt0, lane, acc);
    }

    const int rA = lane >> 2, kq = lane & 3;
    const long r_lo = row0 + wrow + rA, r_hi = r_lo + 8;
    float d_lo = 0.f, d_hi = 0.f;
    if (outs) {
        if (r_lo < NN) d_lo = g_dinv[r_lo];
        if (r_hi < NN) d_hi = g_dinv[r_hi];
    }
#pragma unroll
    for (int nt = 0; nt < 4; nt++) {
        int col = (nt0 + nt) * 8 + kq * 2;
        float2 v0 = make_float2(acc[nt][0] + bsh[col], acc[nt][1] + bsh[col + 1]);
        float2 v1 = make_float2(acc[nt][2] + bsh[col], acc[nt][3] + bsh[col + 1]);
        if (do_relu) {
            v0.x = fmaxf(v0.x, 0.f); v0.y = fmaxf(v0.y, 0.f);
            v1.x = fmaxf(v1.x, 0.f); v1.y = fmaxf(v1.y, 0.f);
        }
        if (r_lo < NN) {
            if (out)  *(float2*)(out  + r_lo * 64 + col) = v0;
            if (outs) *(float2*)(outs + r_lo * 64 + col) = make_float2(v0.x * d_lo, v0.y * d_lo);
        }
        if (r_hi < NN) {
            if (out)  *(float2*)(out  + r_hi * 64 + col) = v1;
            if (outs) *(float2*)(outs + r_hi * 64 + col) = make_float2(v1.x * d_hi, v1.y * d_hi);
        }
    }
}

// =========== fused front MLP + bucket build ===========
__global__ void __launch_bounds__(512) front_build_kernel(const float* __restrict__ X,
                                                          const float* __restrict__ W1,
                                                          const float* __restrict__ b1,
                                                          const float* __restrict__ W2,
                                                          const float* __restrict__ b2,
                                                          float* __restrict__ out,
                                                          const int* __restrict__ src,
                                                          const int* __restrict__ dst) {
    extern __shared__ uint32_t sm[];
    const int b = blockIdx.x;
    const int tid = threadIdx.x;

    if (b >= GT) {                               // bucket build
        int e = (b - GT) * 512 + tid;
        if (e < EE) {
            int d = dst[e];
            int p = atomicAdd(&g_cnt[d], 1);
            if (p < BCAP) g_bucket[(size_t)d * BCAP + p] = src[e];
        }
        return;
    }

    constexpr int PW1 = 68, TA1 = 128 * PW1, TB1 = 64 * PW1;
    constexpr int PW2 = 36, TA2 = 128 * PW2, TB2 = 64 * PW2;
    __shared__ float bsh1[64], bsh2[64];
    const long row0 = (long)b * 128;
    if (tid < 64) { bsh1[tid] = b1[tid]; bsh2[tid] = b2[tid]; }

    for (int q = tid; q < 128 * 32; q += 512) {
        int r = q >> 5, c = (q & 31) * 4;
        long gr = row0 + r; if (gr >= NN) gr = NN - 1;
        float4 v = *(const float4*)(X + gr * 128 + c);
        split4store(sm, sm + TA1, r * PW1 + (c >> 1), v);
    }
    for (int q = tid; q < 64 * 32; q += 512) {
        int r = q >> 5, c = (q & 31) * 4;
        float4 v = *(const float4*)(W1 + (long)r * 128 + c);
        split4store(sm + 2 * TA1, sm + 2 * TA1 + TB1, r * PW1 + (c >> 1), v);
    }
    __syncthreads();

    const int warp = tid >> 5, lane = tid & 31;
    const int wrow = (warp & 7) * 16;
    const int nt0 = (warp >> 3) * 4;
    const uint32_t smbase = (uint32_t)__cvta_generic_to_shared(sm);

    float acc[4][4];
#pragma unroll
    for (int nt = 0; nt < 4; nt++)
#pragma unroll
        for (int j = 0; j < 4; j++) acc[nt][j] = 0.f;
    run_mainloop<PW1, 8>(smbase, TA1, TB1, 2 * TA1, wrow, nt0, lane, acc);
    __syncthreads();

    {   // h1 = relu(acc+b1) -> restage as KD=64 tiles (overlay)
        const int rA = lane >> 2, kq = lane & 3;
        const int rlo = wrow + rA, rhi = rlo + 8;
#pragma unroll
        for (int nt = 0; nt < 4; nt++) {
            int col = (nt0 + nt) * 8 + kq * 2;
            float v0x = fmaxf(acc[nt][0] + bsh1[col], 0.f);
            float v0y = fmaxf(acc[nt][1] + bsh1[col + 1], 0.f);
            float v1x = fmaxf(acc[nt][2] + bsh1[col], 0.f);
            float v1y = fmaxf(acc[nt][3] + bsh1[col + 1], 0.f);
            int w = col >> 1;
            uint32_t h0, l0, h1, l1;
            split2(v0x, v0y, h0, l0);
            split2(v1x, v1y, h1, l1);
            sm[rlo * PW2 + w]       = h0;
            sm[TA2 + rlo * PW2 + w] = l0;
            sm[rhi * PW2 + w]       = h1;
            sm[TA2 + rhi * PW2 + w] = l1;
        }
    }
    for (int q = tid; q < 64 * 16; q += 512) {
        int r = q >> 4, c = (q & 15) * 4;
        float4 v = *(const float4*)(W2 + (long)r * 64 + c);
        split4store(sm + 2 * TA2, sm + 2 * TA2 + TB2, r * PW2 + (c >> 1), v);
    }
    __syncthreads();

    float acc2[4][4];
#pragma unroll
    for (int nt = 0; nt < 4; nt++)
#pragma unroll
        for (int j = 0; j < 4; j++) acc2[nt][j] = 0.f;
    run_mainloop<PW2, 4>(smbase, TA2, TB2, 2 * TA2, wrow, nt0, lane, acc2);

    const int rA = lane >> 2, kq = lane & 3;
    const long r_lo = row0 + wrow + rA, r_hi = r_lo + 8;
#pragma unroll
    for (int nt = 0; nt < 4; nt++) {
        int col = (nt0 + nt) * 8 + kq * 2;
        float2 v0 = make_float2(fmaxf(acc2[nt][0] + bsh2[col], 0.f),
                                fmaxf(acc2[nt][1] + bsh2[col + 1], 0.f));
        float2 v1 = make_float2(fmaxf(acc2[nt][2] + bsh2[col], 0.f),
                                fmaxf(acc2[nt][3] + bsh2[col + 1], 0.f));
        if (r_lo < NN) *(float2*)(out + r_lo * 64 + col) = v0;
        if (r_hi < NN) *(float2*)(out + r_hi * 64 + col) = v1;
    }
}

// =========== fused back MLP + head ===========
__global__ void __launch_bounds__(512) mlp_back_kernel(const float* __restrict__ X,
                                                       const float* __restrict__ W3,
                                                       const float* __restrict__ b3,
                                                       const float* __restrict__ W4,
                                                       const float* __restrict__ b4,
                                                       float* __restrict__ out) {
    constexpr int PW = 36, TA = 128 * PW, TB = 64 * PW;
    extern __shared__ uint32_t sm[];
    __shared__ float bsh[64], W4sh[128], b4sh[2];
    __shared__ float hp[2][128][2];

    const int tid = threadIdx.x;
    const long row0 = (long)blockIdx.x * 128;
    if (tid < 64)  bsh[tid] = b3[tid];
    if (tid < 128) W4sh[tid] = W4[tid];
    if (tid < 2)   b4sh[tid] = b4[tid];

    for (int q = tid; q < 128 * 16; q += 512) {
        int r = q >> 4, c = (q & 15) * 4;
        long gr = row0 + r; if (gr >= NN) gr = NN - 1;
        float4 v = *(const float4*)(X + gr * 64 + c);
        split4store(sm, sm + TA, r * PW + (c >> 1), v);
    }
    for (int q = tid; q < 64 * 16; q += 512) {
        int r = q >> 4, c = (q & 15) * 4;
        float4 v = *(const float4*)(W3 + (long)r * 64 + c);
        split4store(sm + 2 * TA, sm + 2 * TA + TB, r * PW + (c >> 1), v);
    }
    __syncthreads();

    const int warp = tid >> 5, lane = tid & 31;
    const int wrow = (warp & 7) * 16;
    const int nt0w = warp >> 3;
    const int nt0 = nt0w * 4;
    const uint32_t smbase = (uint32_t)__cvta_generic_to_shared(sm);

    float acc[4][4];
#pragma unroll
    for (int nt = 0; nt < 4; nt++)
#pragma unroll
        for (int j = 0; j < 4; j++) acc[nt][j] = 0.f;
    run_mainloop<PW, 4>(smbase, TA, TB, 2 * TA, wrow, nt0, lane, acc);

    const int rA = lane >> 2, kq = lane & 3;
    float p00 = 0.f, p01 = 0.f, p10 = 0.f, p11 = 0.f;
#pragma unroll
    for (int nt = 0; nt < 4; nt++) {
        int c = (nt0 + nt) * 8 + kq * 2;
        float v0x = fmaxf(acc[nt][0] + bsh[c], 0.f);
        float v0y = fmaxf(acc[nt][1] + bsh[c + 1], 0.f);
        float v1x = fmaxf(acc[nt][2] + bsh[c], 0.f);
        float v1y = fmaxf(acc[nt][3] + bsh[c + 1], 0.f);
        float w0a = W4sh[c], w0b = W4sh[c + 1];
        float w1a = W4sh[64 + c], w1b = W4sh[64 + c + 1];
        p00 = fmaf(v0x, w0a, fmaf(v0y, w0b, p00));
        p01 = fmaf(v0x, w1a, fmaf(v0y, w1b, p01));
        p10 = fmaf(v1x, w0a, fmaf(v1y, w0b, p10));
        p11 = fmaf(v1x, w1a, fmaf(v1y, w1b, p11));
    }
    p00 += __shfl_xor_sync(0xffffffffu, p00, 1); p00 += __shfl_xor_sync(0xffffffffu, p00, 2);
    p01 += __shfl_xor_sync(0xffffffffu, p01, 1); p01 += __shfl_xor_sync(0xffffffffu, p01, 2);
    p10 += __shfl_xor_sync(0xffffffffu, p10, 1); p10 += __shfl_xor_sync(0xffffffffu, p10, 2);
    p11 += __shfl_xor_sync(0xffffffffu, p11, 1); p11 += __shfl_xor_sync(0xffffffffu, p11, 2);
    if (kq == 0) {
        hp[nt0w][wrow + rA][0] = p00;
        hp[nt0w][wrow + rA][1] = p01;
        hp[nt0w][wrow + rA + 8][0] = p10;
        hp[nt0w][wrow + rA + 8][1] = p11;
    }
    __syncthreads();
    if (tid < 256) {
        int row = tid >> 1, cls = tid & 1;
        long gr = row0 + row;
        if (gr < NN) out[gr * 2 + cls] = hp[0][row][cls] + hp[1][row][cls] + b4sh[cls];
    }
}

// ------------- SpMM on pre-scaled input: S[n,:] = dinv[n] * sum_{e: dst=n} Xs[src,:] -------------
// Writes unscaled S (SoutU) and/or scaled S*dinv (SoutS); either may be null.
__global__ void __launch_bounds__(256) spmm_norm_kernel(const float* __restrict__ Xs,
                                                        float* __restrict__ SoutU,
                                                        float* __restrict__ SoutS) {
    int n = (blockIdx.x * 256 + threadIdx.x) >> 5;
    if (n >= NN) return;
    int lane = threadIdx.x & 31;
    int cnt = g_cnt[n];
    if (cnt > BCAP) cnt = BCAP;
    const int4* bk4 = (const int4*)&g_bucket[(size_t)n * BCAP];
    const float* xb = Xs + (size_t)lane * 2;
    float2 a0 = make_float2(0.f, 0.f), a1 = make_float2(0.f, 0.f);
    float2 a2 = make_float2(0.f, 0.f), a3 = make_float2(0.f, 0.f);
    int i = 0;
    for (; i + 3 < cnt; i += 4) {
        int4 s4 = bk4[i >> 2];
        float2 v0 = *(const float2*)(xb + (size_t)s4.x * 64);
        float2 v1 = *(const float2*)(xb + (size_t)s4.y * 64);
        float2 v2 = *(const float2*)(xb + (size_t)s4.z * 64);
        float2 v3 = *(const float2*)(xb + (size_t)s4.w * 64);
        a0.x += v0.x; a0.y += v0.y;
        a1.x += v1.x; a1.y += v1.y;
        a2.x += v2.x; a2.y += v2.y;
        a3.x += v3.x; a3.y += v3.y;
    }
    const int* bk = (const int*)bk4;
    for (; i < cnt; i++) {
        int s = bk[i];
        float2 v = *(const float2*)(xb + (size_t)s * 64);
        a0.x += v.x; a0.y += v.y;
    }
    float dn = g_dinv[n];
    float2 acc;
    acc.x = ((a0.x + a1.x) + (a2.x + a3.x)) * dn;
    acc.y = ((a0.y + a1.y) + (a2.y + a3.y)) * dn;
    if (SoutU)
        *(float2*)(SoutU + (size_t)n * 64 + lane * 2) = acc;
    if (SoutS)
        *(float2*)(SoutS + (size_t)n * 64 + lane * 2) = make_float2(acc.x * dn, acc.y * dn);
}

// ---------------- launch ----------------
extern "C" void kernel_launch(void* const* d_in, const int* in_sizes, int n_in,
                              void* d_out, int out_size) {
    const float* in_feat = (const float*)d_in[0];
    const int*   src     = (const int*)d_in[1];
    const int*   dst     = (const int*)d_in[2];
    const float* W1  = (const float*)d_in[3];
    const float* b1  = (const float*)d_in[4];
    const float* W2  = (const float*)d_in[5];
    const float* b2  = (const float*)d_in[6];
    const float* Wc1 = (const float*)d_in[7];
    const float* bc1 = (const float*)d_in[8];
    const float* Wc2 = (const float*)d_in[9];
    const float* bc2 = (const float*)d_in[10];
    const float* W3  = (const float*)d_in[11];
    const float* b3  = (const float*)d_in[12];
    const float* W4  = (const float*)d_in[13];
    const float* b4  = (const float*)d_in[14];
    float* out = (float*)d_out;

    float *h2, *h2s, *S1s, *S2, *c1s, *c2;
    int* cnt;
    cudaGetSymbolAddress((void**)&h2,  g_h2);
    cudaGetSymbolAddress((void**)&h2s, g_h2s);
    cudaGetSymbolAddress((void**)&S1s, g_S1s);
    cudaGetSymbolAddress((void**)&S2,  g_S2);
    cudaGetSymbolAddress((void**)&c1s, g_c1s);
    cudaGetSymbolAddress((void**)&c2,  g_c2);
    cudaGetSymbolAddress((void**)&cnt, g_cnt);

    const int FRONT_SMEM = (2 * 128 * 68 + 2 * 64 * 68) * 4;   // 104448
    const int BACK_SMEM  = (2 * 128 * 36 + 2 * 64 * 36) * 4;   // 55296
    const int CAT_SMEM   = (2 * 128 * 52 + 2 * 64 * 52) * 4;   // 79872

    cudaFuncSetAttribute(front_build_kernel, cudaFuncAttributeMaxDynamicSharedMemorySize, FRONT_SMEM);
    cudaFuncSetAttribute(mlp_back_kernel,    cudaFuncAttributeMaxDynamicSharedMemorySize, BACK_SMEM);
    cudaFuncSetAttribute(gemm_mma_kernel<192, 96, 1>, cudaFuncAttributeMaxDynamicSharedMemorySize, CAT_SMEM);
    cudaFuncSetAttribute(gemm_mma_kernel<192, 96, 2>, cudaFuncAttributeMaxDynamicSharedMemorySize, CAT_SMEM);

    const int GW = (NN * 32 + 255) / 256;   // warp-per-node kernels

    // zero counts, then fused front-MLP || bucket-build
    cudaMemsetAsync(cnt, 0, NN * sizeof(int));
    front_build_kernel<<<GT + GB, 512, FRONT_SMEM>>>(in_feat, W1, b1, W2, b2, h2, src, dst);
    dinv_scale_kernel<<<GW, 256>>>(h2, h2s);     // g_dinv, g_drt, h2s = h2*dinv

    // ChebConv 1: S1s = a_norm(h2)*dinv; S2 = a_norm(S1); c1s = relu(cat@Wc1+b)*dinv
    spmm_norm_kernel<<<GW, 256>>>(h2s, nullptr, S1s);
    spmm_norm_kernel<<<GW, 256>>>(S1s, S2, nullptr);
    gemm_mma_kernel<192, 96, 1><<<GT, 512, CAT_SMEM>>>(h2, S1s, S2, Wc1, bc1, nullptr, c1s, 1);

    // ChebConv 2 (X = c1s, scaled; reconstruct c1 = c1s*drt in staging)
    spmm_norm_kernel<<<GW, 256>>>(c1s, nullptr, S1s);
    spmm_norm_kernel<<<GW, 256>>>(S1s, S2, nullptr);
    gemm_mma_kernel<192, 96, 2><<<GT, 512, CAT_SMEM>>>(c1s, S1s, S2, Wc2, bc2, c2, nullptr, 1);

    // fused back MLP + head
    mlp_back_kernel<<<GT, 512, BACK_SMEM>>>(c2, W3, b3, W4, b4, out);
}